// round 2
// baseline (speedup 1.0000x reference)
#include <cuda_runtime.h>
#include <cuda_bf16.h>
#include <cstdint>

// ---------------------------------------------------------------------------
// Problem constants
// ---------------------------------------------------------------------------
#define NP      63                 // patches per dim
#define NPATCH  3969               // 63*63
#define BATCH   4
#define BL      15876              // BATCH * NPATCH
#define MPAD    16000              // 125 * 128
#define IND     4096               // C*8*8
#define HIDD    256

// ---------------------------------------------------------------------------
// Scratch (static __device__ arrays: allocation-free per harness rules)
// ---------------------------------------------------------------------------
__device__ __nv_bfloat16 g_P[(size_t)MPAD * IND];    // patches, bf16
__device__ __nv_bfloat16 g_H[(size_t)MPAD * HIDD];   // hidden, bf16
__device__ __nv_bfloat16 g_Y[(size_t)MPAD * IND];    // mlp output, bf16
__device__ __nv_bfloat16 g_W1[(size_t)HIDD * IND];
__device__ __nv_bfloat16 g_W2[(size_t)IND * HIDD];

// ---------------------------------------------------------------------------
// PTX helpers
// ---------------------------------------------------------------------------
__device__ __forceinline__ void cp_async16(uint32_t s, const void* g) {
    asm volatile("cp.async.cg.shared.global [%0], [%1], 16;\n" ::"r"(s), "l"(g));
}
__device__ __forceinline__ void cp_commit() {
    asm volatile("cp.async.commit_group;\n");
}
template <int N>
__device__ __forceinline__ void cp_wait() {
    asm volatile("cp.async.wait_group %0;\n" ::"n"(N));
}
__device__ __forceinline__ void ldmx4(uint32_t& r0, uint32_t& r1, uint32_t& r2,
                                      uint32_t& r3, uint32_t addr) {
    asm volatile("ldmatrix.sync.aligned.m8n8.x4.shared.b16 {%0,%1,%2,%3}, [%4];\n"
                 : "=r"(r0), "=r"(r1), "=r"(r2), "=r"(r3)
                 : "r"(addr));
}
__device__ __forceinline__ void mma16816(float c[4], const uint32_t a[4],
                                         const uint32_t b[2]) {
    asm volatile(
        "mma.sync.aligned.m16n8k16.row.col.f32.bf16.bf16.f32 "
        "{%0,%1,%2,%3}, {%4,%5,%6,%7}, {%8,%9}, {%0,%1,%2,%3};\n"
        : "+f"(c[0]), "+f"(c[1]), "+f"(c[2]), "+f"(c[3])
        : "r"(a[0]), "r"(a[1]), "r"(a[2]), "r"(a[3]), "r"(b[0]), "r"(b[1]));
}

// Swizzled byte offset inside a 128x32 bf16 tile stored as 64 phys rows of 128B.
// (r,kc): r = tile row 0..127, kc = 16B chunk along k (0..3).
// Conflict-free for both cp.async 16B stores and ldmatrix reads (verified:
// 8 consecutive rows at fixed kc hit 8 distinct 16B bank-granules).
__device__ __forceinline__ uint32_t sw_off(int r, int kc) {
    int pr = r >> 1;
    int pc = (((r & 1) << 2) | kc) ^ (pr & 7);
    return (uint32_t)((pr << 7) + (pc << 4));
}

__device__ __forceinline__ float gelu_exact(float v) {
    return 0.5f * v * (1.0f + erff(v * 0.70710678118654752f));
}

// ---------------------------------------------------------------------------
// Kernel 1: convert weights to bf16 (both are exactly 1048576 elements)
// ---------------------------------------------------------------------------
__global__ void convert_weights(const float* __restrict__ W1,
                                const float* __restrict__ W2) {
    int i = (blockIdx.x * 256 + threadIdx.x) * 4;  // grid covers 1048576 exactly
    float4 a = *(const float4*)(W1 + i);
    float4 b = *(const float4*)(W2 + i);
    union { uint2 u; __nv_bfloat162 h[2]; } pa, pb;
    pa.h[0] = __floats2bfloat162_rn(a.x, a.y);
    pa.h[1] = __floats2bfloat162_rn(a.z, a.w);
    pb.h[0] = __floats2bfloat162_rn(b.x, b.y);
    pb.h[1] = __floats2bfloat162_rn(b.z, b.w);
    *(uint2*)(g_W1 + i) = pa.u;
    *(uint2*)(g_W2 + i) = pb.u;
}

// ---------------------------------------------------------------------------
// Kernel 2: patchify  x(f32, B,C,256,256) -> P(bf16, MPAD x 4096)
// P[m][c*64 + kh*8 + kw] = x[b, c, ih*4+kh, iw*4+kw], rows >= BL zero-filled.
// One thread = one (m, c, kh) -> 8 contiguous pixels (two float4 reads, one
// uint4 write).
// ---------------------------------------------------------------------------
__global__ void patchify(const float* __restrict__ x) {
    int gid = blockIdx.x * 256 + threadIdx.x;  // MPAD*512 = 8,192,000 exactly
    int m = gid >> 9;
    int ck = gid & 511;
    union { uint4 u; __nv_bfloat162 h[4]; } val;
    val.u = make_uint4(0u, 0u, 0u, 0u);
    if (m < BL) {
        int b = m / NPATCH;
        int l = m - b * NPATCH;
        int ih = l / NP;
        int iw = l - ih * NP;
        int c = ck >> 3;
        int kh = ck & 7;
        const float* src =
            x + ((((size_t)b * 64 + c) * 256 + (ih * 4 + kh)) * 256 + iw * 4);
        float4 f0 = *(const float4*)src;
        float4 f1 = *(const float4*)(src + 4);
        val.h[0] = __floats2bfloat162_rn(f0.x, f0.y);
        val.h[1] = __floats2bfloat162_rn(f0.z, f0.w);
        val.h[2] = __floats2bfloat162_rn(f1.x, f1.y);
        val.h[3] = __floats2bfloat162_rn(f1.z, f1.w);
    }
    *(uint4*)(g_P + (size_t)m * IND + ck * 8) = val.u;
}

// ---------------------------------------------------------------------------
// Kernel 3: bf16 GEMM  C[M,N] = A[M,K] @ B[N,K]^T (+bias, optional GELU)
// 128x128x32 tiles, 8 warps (4x2), warp tile 32x64, 3-stage cp.async.
// M is always a multiple of 128 (16000), N in {256,4096}, K in {4096,256}.
// ---------------------------------------------------------------------------
template <bool GELU>
__global__ void __launch_bounds__(256, 1)
gemm_bf16(const __nv_bfloat16* __restrict__ A, const __nv_bfloat16* __restrict__ Bw,
          const float* __restrict__ bias, __nv_bfloat16* __restrict__ C,
          int K, int N) {
    constexpr int STAGES = 3;
    constexpr int STAGE_BYTES = 16384;  // A 8KB + B 8KB
    __shared__ __align__(128) uint8_t smem_raw[STAGES * STAGE_BYTES];
    const uint32_t smem = (uint32_t)__cvta_generic_to_shared(smem_raw);

    const int tid = threadIdx.x;
    const int lane = tid & 31, warp = tid >> 5;
    const int wm = warp >> 1, wn = warp & 1;
    const long bm = (long)blockIdx.x * 128;
    const long bn = (long)blockIdx.y * 128;

    float acc[2][8][4];
#pragma unroll
    for (int i = 0; i < 2; i++)
#pragma unroll
        for (int j = 0; j < 8; j++)
#pragma unroll
            for (int k = 0; k < 4; k++) acc[i][j][k] = 0.0f;

    const int KT = K >> 5;

    auto load_stage = [&](int kt, int s) {
        const __nv_bfloat16* Ag = A + bm * K + kt * 32;
        const __nv_bfloat16* Bg = Bw + bn * K + kt * 32;
        uint32_t sA = smem + s * STAGE_BYTES;
        uint32_t sB = sA + 8192;
#pragma unroll
        for (int i = 0; i < 2; i++) {
            int q = tid + (i << 8);
            int r = q >> 2, kc = q & 3;
            cp_async16(sA + sw_off(r, kc), Ag + (long)r * K + (kc << 3));
        }
#pragma unroll
        for (int i = 0; i < 2; i++) {
            int q = tid + (i << 8);
            int r = q >> 2, kc = q & 3;
            cp_async16(sB + sw_off(r, kc), Bg + (long)r * K + (kc << 3));
        }
    };

    load_stage(0, 0); cp_commit();
    if (KT > 1) load_stage(1, 1);
    cp_commit();

    for (int kt = 0; kt < KT; kt++) {
        cp_wait<1>();
        __syncthreads();
        int kn = kt + 2;
        if (kn < KT) load_stage(kn, kn % STAGES);
        cp_commit();

        uint32_t sA = smem + (kt % STAGES) * STAGE_BYTES;
        uint32_t sB = sA + 8192;
#pragma unroll
        for (int kk = 0; kk < 2; kk++) {
            uint32_t a[2][4];
#pragma unroll
            for (int mi = 0; mi < 2; mi++) {
                int r = wm * 32 + mi * 16 + (lane & 15);
                int kc = (kk << 1) | (lane >> 4);
                ldmx4(a[mi][0], a[mi][1], a[mi][2], a[mi][3], sA + sw_off(r, kc));
            }
            uint32_t bfr[8][2];
#pragma unroll
            for (int nj = 0; nj < 4; nj++) {
                int r = wn * 64 + nj * 16 + (lane & 7) + ((lane & 16) >> 1);
                int kc = (kk << 1) | ((lane >> 3) & 1);
                uint32_t t0, t1, t2, t3;
                ldmx4(t0, t1, t2, t3, sB + sw_off(r, kc));
                bfr[nj * 2][0] = t0; bfr[nj * 2][1] = t1;
                bfr[nj * 2 + 1][0] = t2; bfr[nj * 2 + 1][1] = t3;
            }
#pragma unroll
            for (int mi = 0; mi < 2; mi++)
#pragma unroll
                for (int ni = 0; ni < 8; ni++) mma16816(acc[mi][ni], a[mi], bfr[ni]);
        }
    }

    // epilogue: + bias, optional exact GELU, store bf16
    const long crow = bm + wm * 32 + (lane >> 2);
#pragma unroll
    for (int mi = 0; mi < 2; mi++) {
#pragma unroll
        for (int ni = 0; ni < 8; ni++) {
            long col = bn + wn * 64 + ni * 8 + ((lane & 3) << 1);
            float b0 = bias[col], b1 = bias[col + 1];
            float v0 = acc[mi][ni][0] + b0;
            float v1 = acc[mi][ni][1] + b1;
            float v2 = acc[mi][ni][2] + b0;
            float v3 = acc[mi][ni][3] + b1;
            if (GELU) {
                v0 = gelu_exact(v0); v1 = gelu_exact(v1);
                v2 = gelu_exact(v2); v3 = gelu_exact(v3);
            }
            long r0 = crow + mi * 16;
            *(__nv_bfloat162*)(C + r0 * N + col) = __floats2bfloat162_rn(v0, v1);
            *(__nv_bfloat162*)(C + (r0 + 8) * N + col) = __floats2bfloat162_rn(v2, v3);
        }
    }
}

// ---------------------------------------------------------------------------
// Kernel 4: gather-fold + residual
// out = x + softplus(alpha_raw) * fold(Y)/norm   (fold(P)/norm == x exactly)
// One thread = 4 consecutive pixels along W (shared patch-column set).
// ---------------------------------------------------------------------------
__global__ void fold_kernel(const float* __restrict__ x,
                            const float* __restrict__ alpha_raw,
                            float* __restrict__ out) {
    int t = blockIdx.x * 256 + threadIdx.x;  // 4,194,304 threads exactly
    int w0 = (t & 63) << 2;
    int h = (t >> 6) & 255;
    int c = (t >> 14) & 63;
    int b = t >> 20;

    float alpha = log1pf(__expf(alpha_raw[0]));

    int ih_lo = max(0, (h - 4) >> 2);       // floor((h-7+3)/4) clamped
    int ih_hi = min(62, h >> 2);
    int iw_lo = max(0, (w0 - 4) >> 2);
    int iw_hi = min(62, w0 >> 2);
    int cnt = (ih_hi - ih_lo + 1) * (iw_hi - iw_lo + 1);

    float s0 = 0.f, s1 = 0.f, s2 = 0.f, s3 = 0.f;
    for (int ih = ih_lo; ih <= ih_hi; ih++) {
        int kh = h - 4 * ih;
        for (int iw = iw_lo; iw <= iw_hi; iw++) {
            int kw0 = w0 - 4 * iw;  // 0 or 4 -> 8B aligned
            size_t m = (size_t)b * NPATCH + ih * NP + iw;
            const __nv_bfloat162* p =
                (const __nv_bfloat162*)(g_Y + m * IND + c * 64 + kh * 8 + kw0);
            __nv_bfloat162 v01 = p[0];
            __nv_bfloat162 v23 = p[1];
            s0 += __low2float(v01); s1 += __high2float(v01);
            s2 += __low2float(v23); s3 += __high2float(v23);
        }
    }
    float sc = alpha / (float)cnt;
    size_t xi = (size_t)t * 4;
    float4 xv = *(const float4*)(x + xi);
    float4 o;
    o.x = fmaf(s0, sc, xv.x);
    o.y = fmaf(s1, sc, xv.y);
    o.z = fmaf(s2, sc, xv.z);
    o.w = fmaf(s3, sc, xv.w);
    *(float4*)(out + xi) = o;
}

// ---------------------------------------------------------------------------
// Launch
// ---------------------------------------------------------------------------
extern "C" void kernel_launch(void* const* d_in, const int* in_sizes, int n_in,
                              void* d_out, int out_size) {
    const float* x         = (const float*)d_in[0];
    const float* W1        = (const float*)d_in[1];
    const float* b1        = (const float*)d_in[2];
    const float* W2        = (const float*)d_in[3];
    const float* b2        = (const float*)d_in[4];
    const float* alpha_raw = (const float*)d_in[5];
    float* out             = (float*)d_out;

    void *pP, *pH, *pY, *pW1, *pW2;
    cudaGetSymbolAddress(&pP, g_P);
    cudaGetSymbolAddress(&pH, g_H);
    cudaGetSymbolAddress(&pY, g_Y);
    cudaGetSymbolAddress(&pW1, g_W1);
    cudaGetSymbolAddress(&pW2, g_W2);

    convert_weights<<<1024, 256>>>(W1, W2);
    patchify<<<32000, 256>>>(x);
    // GEMM1: H = GELU(P @ W1^T + b1)   M=16000, N=256, K=4096
    gemm_bf16<true><<<dim3(125, 2), 256>>>(
        (const __nv_bfloat16*)pP, (const __nv_bfloat16*)pW1, b1,
        (__nv_bfloat16*)pH, 4096, 256);
    // GEMM2: Y = H @ W2^T + b2         M=16000, N=4096, K=256
    gemm_bf16<false><<<dim3(125, 32), 256>>>(
        (const __nv_bfloat16*)pH, (const __nv_bfloat16*)pW2, b2,
        (__nv_bfloat16*)pY, 256, 4096);
    fold_kernel<<<16384, 256>>>(x, alpha_raw, out);
}

// round 4
// speedup vs baseline: 1.1023x; 1.1023x over previous
#include <cuda_runtime.h>
#include <cuda_bf16.h>
#include <cstdint>

// ---------------------------------------------------------------------------
// Problem constants
// ---------------------------------------------------------------------------
#define NP      63                 // patches per dim
#define NPATCH  3969               // 63*63
#define BL      15876              // 4 * 3969
#define MPAD    16000              // 125 * 128
#define IND     4096
#define HIDD    256

// ---------------------------------------------------------------------------
// Scratch
// ---------------------------------------------------------------------------
__device__ __nv_bfloat16 g_P[(size_t)MPAD * IND];
__device__ __nv_bfloat16 g_H[(size_t)MPAD * HIDD];
__device__ __nv_bfloat16 g_Y[(size_t)MPAD * IND];
__device__ __nv_bfloat16 g_W1[(size_t)HIDD * IND];
__device__ __nv_bfloat16 g_W2[(size_t)IND * HIDD];

// ---------------------------------------------------------------------------
// PTX helpers
// ---------------------------------------------------------------------------
__device__ __forceinline__ void cp_async16(uint32_t s, const void* g) {
    asm volatile("cp.async.cg.shared.global [%0], [%1], 16;\n" ::"r"(s), "l"(g));
}
__device__ __forceinline__ void cp_commit() {
    asm volatile("cp.async.commit_group;\n");
}
template <int N>
__device__ __forceinline__ void cp_wait() {
    asm volatile("cp.async.wait_group %0;\n" ::"n"(N));
}
__device__ __forceinline__ void ldmx4(uint32_t& r0, uint32_t& r1, uint32_t& r2,
                                      uint32_t& r3, uint32_t addr) {
    asm volatile("ldmatrix.sync.aligned.m8n8.x4.shared.b16 {%0,%1,%2,%3}, [%4];\n"
                 : "=r"(r0), "=r"(r1), "=r"(r2), "=r"(r3)
                 : "r"(addr));
}
__device__ __forceinline__ void mma16816(float c[4], const uint32_t a[4],
                                         const uint32_t b[2]) {
    asm volatile(
        "mma.sync.aligned.m16n8k16.row.col.f32.bf16.bf16.f32 "
        "{%0,%1,%2,%3}, {%4,%5,%6,%7}, {%8,%9}, {%0,%1,%2,%3};\n"
        : "+f"(c[0]), "+f"(c[1]), "+f"(c[2]), "+f"(c[3])
        : "r"(a[0]), "r"(a[1]), "r"(a[2]), "r"(a[3]), "r"(b[0]), "r"(b[1]));
}

// Swizzled byte offset for an Rx32 bf16 tile stored as R/2 phys rows of 128B.
// (r,kc): r = tile row, kc = 16B chunk along k (0..3). Conflict-free for both
// cp.async 16B stores and ldmatrix reads (verified in R2 passing kernel).
__device__ __forceinline__ uint32_t sw_off(int r, int kc) {
    int pr = r >> 1;
    int pc = (((r & 1) << 2) | kc) ^ (pr & 7);
    return (uint32_t)((pr << 7) + (pc << 4));
}

__device__ __forceinline__ float gelu_exact(float v) {
    return 0.5f * v * (1.0f + erff(v * 0.70710678118654752f));
}

// ---------------------------------------------------------------------------
// Kernel 1: convert weights to bf16 (both exactly 1048576 elems)
// ---------------------------------------------------------------------------
__global__ void convert_weights(const float* __restrict__ W1,
                                const float* __restrict__ W2) {
    int i = (blockIdx.x * 256 + threadIdx.x) * 4;
    float4 a = *(const float4*)(W1 + i);
    float4 b = *(const float4*)(W2 + i);
    union { uint2 u; __nv_bfloat162 h[2]; } pa, pb;
    pa.h[0] = __floats2bfloat162_rn(a.x, a.y);
    pa.h[1] = __floats2bfloat162_rn(a.z, a.w);
    pb.h[0] = __floats2bfloat162_rn(b.x, b.y);
    pb.h[1] = __floats2bfloat162_rn(b.z, b.w);
    *(uint2*)(g_W1 + i) = pa.u;
    *(uint2*)(g_W2 + i) = pb.u;
}

// ---------------------------------------------------------------------------
// Kernel 2: patchify  x(f32) -> P(bf16, MPAD x 4096), rows >= BL zeroed
// ---------------------------------------------------------------------------
__global__ void patchify(const float* __restrict__ x) {
    int gid = blockIdx.x * 256 + threadIdx.x;  // MPAD*512 threads
    int m = gid >> 9;
    int ck = gid & 511;
    union { uint4 u; __nv_bfloat162 h[4]; } val;
    val.u = make_uint4(0u, 0u, 0u, 0u);
    if (m < BL) {
        int b = m / NPATCH;
        int l = m - b * NPATCH;
        int ih = l / NP;
        int iw = l - ih * NP;
        int c = ck >> 3;
        int kh = ck & 7;
        const float* src =
            x + ((((size_t)b * 64 + c) * 256 + (ih * 4 + kh)) * 256 + iw * 4);
        float4 f0 = *(const float4*)src;
        float4 f1 = *(const float4*)(src + 4);
        val.h[0] = __floats2bfloat162_rn(f0.x, f0.y);
        val.h[1] = __floats2bfloat162_rn(f0.z, f0.w);
        val.h[2] = __floats2bfloat162_rn(f1.x, f1.y);
        val.h[3] = __floats2bfloat162_rn(f1.z, f1.w);
    }
    *(uint4*)(g_P + (size_t)m * IND + ck * 8) = val.u;
}

// ---------------------------------------------------------------------------
// Kernel 3: bf16 GEMM  C[M,N] = A[M,K] @ B[N,K]^T (+bias, optional GELU)
// 128x256x32 CTA tile, 512 threads (16 warps, 4x4), warp tile 32x64,
// 4-stage cp.async pipeline. M multiple of 128, N multiple of 256.
// ---------------------------------------------------------------------------
template <bool GELU>
__global__ void __launch_bounds__(512, 1)
gemm_bf16(const __nv_bfloat16* __restrict__ A, const __nv_bfloat16* __restrict__ Bw,
          const float* __restrict__ bias, __nv_bfloat16* __restrict__ C,
          int K, int N) {
    constexpr int STAGES = 4;
    constexpr int ABYTES = 8192;        // 128 x 32 bf16
    constexpr int BBYTES = 16384;       // 256 x 32 bf16
    constexpr int STAGE_BYTES = ABYTES + BBYTES;  // 24 KB
    extern __shared__ __align__(128) uint8_t smem_raw[];
    const uint32_t smem = (uint32_t)__cvta_generic_to_shared(smem_raw);

    const int tid = threadIdx.x;
    const int lane = tid & 31, warp = tid >> 5;
    const int wm = warp >> 2, wn = warp & 3;
    const long bm = (long)blockIdx.x * 128;
    const long bn = (long)blockIdx.y * 256;

    float acc[2][8][4];
#pragma unroll
    for (int i = 0; i < 2; i++)
#pragma unroll
        for (int j = 0; j < 8; j++)
#pragma unroll
            for (int k = 0; k < 4; k++) acc[i][j][k] = 0.0f;

    const int KT = K >> 5;

    auto load_stage = [&](int kt) {
        const __nv_bfloat16* Ag = A + bm * K + kt * 32;
        const __nv_bfloat16* Bg = Bw + bn * K + kt * 32;
        uint32_t sA = smem + (kt % STAGES) * STAGE_BYTES;
        uint32_t sB = sA + ABYTES;
        {   // A: 128 rows x 4 x 16B = 512 chunks, one per thread
            int r = tid >> 2, kc = tid & 3;
            cp_async16(sA + sw_off(r, kc), Ag + (long)r * K + (kc << 3));
        }
#pragma unroll
        for (int i = 0; i < 2; i++) {  // B: 256 rows x 4 x 16B = 1024 chunks
            int q = tid + (i << 9);
            int r = q >> 2, kc = q & 3;
            cp_async16(sB + sw_off(r, kc), Bg + (long)r * K + (kc << 3));
        }
    };

    load_stage(0); cp_commit();
    load_stage(1); cp_commit();
    load_stage(2); cp_commit();

    for (int kt = 0; kt < KT; kt++) {
        if (kt + 2 < KT) cp_wait<2>(); else cp_wait<0>();
        __syncthreads();
        int kn = kt + 3;
        if (kn < KT) load_stage(kn);
        cp_commit();

        uint32_t sA = smem + (kt % STAGES) * STAGE_BYTES;
        uint32_t sB = sA + ABYTES;
#pragma unroll
        for (int kk = 0; kk < 2; kk++) {
            uint32_t a[2][4];
#pragma unroll
            for (int mi = 0; mi < 2; mi++) {
                int r = wm * 32 + mi * 16 + (lane & 15);
                int kc = (kk << 1) | (lane >> 4);
                ldmx4(a[mi][0], a[mi][1], a[mi][2], a[mi][3], sA + sw_off(r, kc));
            }
            uint32_t bfr[8][2];
#pragma unroll
            for (int nj = 0; nj < 4; nj++) {
                int r = wn * 64 + nj * 16 + (lane & 7) + ((lane & 16) >> 1);
                int kc = (kk << 1) | ((lane >> 3) & 1);
                uint32_t t0, t1, t2, t3;
                ldmx4(t0, t1, t2, t3, sB + sw_off(r, kc));
                bfr[nj * 2][0] = t0; bfr[nj * 2][1] = t1;
                bfr[nj * 2 + 1][0] = t2; bfr[nj * 2 + 1][1] = t3;
            }
#pragma unroll
            for (int mi = 0; mi < 2; mi++)
#pragma unroll
                for (int ni = 0; ni < 8; ni++) mma16816(acc[mi][ni], a[mi], bfr[ni]);
        }
    }

    // epilogue: + bias, optional exact GELU, store bf16
    const long crow = bm + wm * 32 + (lane >> 2);
#pragma unroll
    for (int mi = 0; mi < 2; mi++) {
#pragma unroll
        for (int ni = 0; ni < 8; ni++) {
            long col = bn + wn * 64 + ni * 8 + ((lane & 3) << 1);
            float b0 = bias[col], b1 = bias[col + 1];
            float v0 = acc[mi][ni][0] + b0;
            float v1 = acc[mi][ni][1] + b1;
            float v2 = acc[mi][ni][2] + b0;
            float v3 = acc[mi][ni][3] + b1;
            if (GELU) {
                v0 = gelu_exact(v0); v1 = gelu_exact(v1);
                v2 = gelu_exact(v2); v3 = gelu_exact(v3);
            }
            long r0 = crow + mi * 16;
            *(__nv_bfloat162*)(C + r0 * N + col) = __floats2bfloat162_rn(v0, v1);
            *(__nv_bfloat162*)(C + (r0 + 8) * N + col) = __floats2bfloat162_rn(v2, v3);
        }
    }
}

// ---------------------------------------------------------------------------
// Kernel 4: gather-fold + residual
// out = x + softplus(alpha_raw) * fold(Y)/norm   (fold(P)/norm == x exactly)
// ---------------------------------------------------------------------------
__global__ void fold_kernel(const float* __restrict__ x,
                            const float* __restrict__ alpha_raw,
                            float* __restrict__ out) {
    int t = blockIdx.x * 256 + threadIdx.x;  // 4,194,304 threads
    int w0 = (t & 63) << 2;
    int h = (t >> 6) & 255;
    int c = (t >> 14) & 63;
    int b = t >> 20;

    float alpha = log1pf(__expf(alpha_raw[0]));

    int ih_lo = max(0, (h - 4) >> 2);
    int ih_hi = min(62, h >> 2);
    int iw_lo = max(0, (w0 - 4) >> 2);
    int iw_hi = min(62, w0 >> 2);
    int cnt = (ih_hi - ih_lo + 1) * (iw_hi - iw_lo + 1);

    float s0 = 0.f, s1 = 0.f, s2 = 0.f, s3 = 0.f;
    for (int ih = ih_lo; ih <= ih_hi; ih++) {
        int kh = h - 4 * ih;
        for (int iw = iw_lo; iw <= iw_hi; iw++) {
            int kw0 = w0 - 4 * iw;
            size_t m = (size_t)b * NPATCH + ih * NP + iw;
            const __nv_bfloat162* p =
                (const __nv_bfloat162*)(g_Y + m * IND + c * 64 + kh * 8 + kw0);
            __nv_bfloat162 v01 = p[0];
            __nv_bfloat162 v23 = p[1];
            s0 += __low2float(v01); s1 += __high2float(v01);
            s2 += __low2float(v23); s3 += __high2float(v23);
        }
    }
    float sc = alpha / (float)cnt;
    size_t xi = (size_t)t * 4;
    float4 xv = *(const float4*)(x + xi);
    float4 o;
    o.x = fmaf(s0, sc, xv.x);
    o.y = fmaf(s1, sc, xv.y);
    o.z = fmaf(s2, sc, xv.z);
    o.w = fmaf(s3, sc, xv.w);
    *(float4*)(out + xi) = o;
}

// ---------------------------------------------------------------------------
// Launch
// ---------------------------------------------------------------------------
extern "C" void kernel_launch(void* const* d_in, const int* in_sizes, int n_in,
                              void* d_out, int out_size) {
    const float* x         = (const float*)d_in[0];
    const float* W1        = (const float*)d_in[1];
    const float* b1        = (const float*)d_in[2];
    const float* W2        = (const float*)d_in[3];
    const float* b2        = (const float*)d_in[4];
    const float* alpha_raw = (const float*)d_in[5];
    float* out             = (float*)d_out;

    void *pP, *pH, *pY, *pW1, *pW2;
    cudaGetSymbolAddress(&pP, g_P);
    cudaGetSymbolAddress(&pH, g_H);
    cudaGetSymbolAddress(&pY, g_Y);
    cudaGetSymbolAddress(&pW1, g_W1);
    cudaGetSymbolAddress(&pW2, g_W2);

    const int SMEMSZ = 4 * 24576;  // 96 KB
    cudaFuncSetAttribute(gemm_bf16<true>,
                         cudaFuncAttributeMaxDynamicSharedMemorySize, SMEMSZ);
    cudaFuncSetAttribute(gemm_bf16<false>,
                         cudaFuncAttributeMaxDynamicSharedMemorySize, SMEMSZ);

    convert_weights<<<1024, 256>>>(W1, W2);
    patchify<<<32000, 256>>>(x);
    // GEMM1: H = GELU(P @ W1^T + b1)   M=16000, N=256, K=4096
    gemm_bf16<true><<<dim3(125, 1), 512, SMEMSZ>>>(
        (const __nv_bfloat16*)pP, (const __nv_bfloat16*)pW1, b1,
        (__nv_bfloat16*)pH, 4096, 256);
    // GEMM2: Y = H @ W2^T + b2         M=16000, N=4096, K=256
    gemm_bf16<false><<<dim3(125, 16), 512, SMEMSZ>>>(
        (const __nv_bfloat16*)pH, (const __nv_bfloat16*)pW2, b2,
        (__nv_bfloat16*)pY, 256, 4096);
    fold_kernel<<<16384, 256>>>(x, alpha_raw, out);
}

// round 5
// speedup vs baseline: 1.2336x; 1.1191x over previous
#include <cuda_runtime.h>
#include <cuda_bf16.h>
#include <cstdint>

// ---------------------------------------------------------------------------
// Problem constants
// ---------------------------------------------------------------------------
#define NP      63                 // patches per dim
#define NPATCH  3969               // 63*63
#define BL      15876              // 4 * 3969
#define MPAD    16000              // 125 * 128
#define IND     4096
#define HIDD    256

// ---------------------------------------------------------------------------
// Scratch
// ---------------------------------------------------------------------------
__device__ __nv_bfloat16 g_Xb[(size_t)4 * 64 * 256 * 256];  // x in bf16
__device__ __nv_bfloat16 g_H[(size_t)MPAD * HIDD];
__device__ __nv_bfloat16 g_Y[(size_t)MPAD * IND];
__device__ __nv_bfloat16 g_W1[(size_t)HIDD * IND];
__device__ __nv_bfloat16 g_W2[(size_t)IND * HIDD];

// ---------------------------------------------------------------------------
// PTX helpers
// ---------------------------------------------------------------------------
__device__ __forceinline__ void cp_async16(uint32_t s, const void* g) {
    asm volatile("cp.async.cg.shared.global [%0], [%1], 16;\n" ::"r"(s), "l"(g));
}
// 8-byte cp.async with zero-fill: copies sz bytes (0 or 8), zero-pads to 8.
__device__ __forceinline__ void cp_async8z(uint32_t s, const void* g, uint32_t sz) {
    asm volatile("cp.async.ca.shared.global [%0], [%1], 8, %2;\n"
                 ::"r"(s), "l"(g), "r"(sz));
}
__device__ __forceinline__ void cp_commit() {
    asm volatile("cp.async.commit_group;\n");
}
template <int N>
__device__ __forceinline__ void cp_wait() {
    asm volatile("cp.async.wait_group %0;\n" ::"n"(N));
}
__device__ __forceinline__ void ldmx4(uint32_t& r0, uint32_t& r1, uint32_t& r2,
                                      uint32_t& r3, uint32_t addr) {
    asm volatile("ldmatrix.sync.aligned.m8n8.x4.shared.b16 {%0,%1,%2,%3}, [%4];\n"
                 : "=r"(r0), "=r"(r1), "=r"(r2), "=r"(r3)
                 : "r"(addr));
}
__device__ __forceinline__ void mma16816(float c[4], const uint32_t a[4],
                                         const uint32_t b[2]) {
    asm volatile(
        "mma.sync.aligned.m16n8k16.row.col.f32.bf16.bf16.f32 "
        "{%0,%1,%2,%3}, {%4,%5,%6,%7}, {%8,%9}, {%0,%1,%2,%3};\n"
        : "+f"(c[0]), "+f"(c[1]), "+f"(c[2]), "+f"(c[3])
        : "r"(a[0]), "r"(a[1]), "r"(a[2]), "r"(a[3]), "r"(b[0]), "r"(b[1]));
}

// Swizzled byte offset for an Rx32 bf16 tile stored as R/2 phys rows of 128B.
// (r,kc): r = tile row, kc = 16B chunk along k (0..3). Conflict-free for
// cp.async stores and ldmatrix reads (verified in passing R2/R4 kernels).
__device__ __forceinline__ uint32_t sw_off(int r, int kc) {
    int pr = r >> 1;
    int pc = (((r & 1) << 2) | kc) ^ (pr & 7);
    return (uint32_t)((pr << 7) + (pc << 4));
}

__device__ __forceinline__ float gelu_exact(float v) {
    return 0.5f * v * (1.0f + erff(v * 0.70710678118654752f));
}

// ---------------------------------------------------------------------------
// Kernel 1a: convert weights to bf16 (both exactly 1048576 elems)
// ---------------------------------------------------------------------------
__global__ void convert_weights(const float* __restrict__ W1,
                                const float* __restrict__ W2) {
    int i = (blockIdx.x * 256 + threadIdx.x) * 4;
    float4 a = *(const float4*)(W1 + i);
    float4 b = *(const float4*)(W2 + i);
    union { uint2 u; __nv_bfloat162 h[2]; } pa, pb;
    pa.h[0] = __floats2bfloat162_rn(a.x, a.y);
    pa.h[1] = __floats2bfloat162_rn(a.z, a.w);
    pb.h[0] = __floats2bfloat162_rn(b.x, b.y);
    pb.h[1] = __floats2bfloat162_rn(b.z, b.w);
    *(uint2*)(g_W1 + i) = pa.u;
    *(uint2*)(g_W2 + i) = pb.u;
}

// ---------------------------------------------------------------------------
// Kernel 1b: convert x to bf16 (16,777,216 elems)
// ---------------------------------------------------------------------------
__global__ void convert_x(const float* __restrict__ x) {
    int i = (blockIdx.x * 256 + threadIdx.x) * 4;
    float4 f = *(const float4*)(x + i);
    union { uint2 u; __nv_bfloat162 h[2]; } v;
    v.h[0] = __floats2bfloat162_rn(f.x, f.y);
    v.h[1] = __floats2bfloat162_rn(f.z, f.w);
    *(uint2*)(g_Xb + i) = v.u;
}

// ---------------------------------------------------------------------------
// Kernel 2: GEMM1 fused with patchify.
// H = GELU(P @ W1^T + b1), P[m][c*64+kh*8+kw] = Xb[b,c,ih*4+kh,iw*4+kw]
// gathered on the fly from g_Xb. CTA tile 128x256x32, 512 threads, 4 stages.
// K-chunk kt covers c = kt>>1, kh0 = (kt&1)*4; thread chunk (r=tid>>2,
// kc=tid&3) is 8 pixels at row kh0+kc -> two 8B zfill cp.asyncs.
// ---------------------------------------------------------------------------
__global__ void __launch_bounds__(512, 1)
gemm1_fused(const float* __restrict__ bias, __nv_bfloat16* __restrict__ H) {
    constexpr int ABYTES = 8192;        // 128 x 32 bf16
    constexpr int BBYTES = 16384;       // 256 x 32 bf16
    constexpr int STAGE_BYTES = ABYTES + BBYTES;  // 24 KB, 4 stages = 96 KB
    extern __shared__ __align__(128) uint8_t smem_raw[];
    const uint32_t smem = (uint32_t)__cvta_generic_to_shared(smem_raw);

    const int tid = threadIdx.x;
    const int lane = tid & 31, warp = tid >> 5;
    const int wm = warp >> 2, wn = warp & 3;
    const int bm = blockIdx.x * 128;
    constexpr int K = 4096, N = 256, KT = 128;

    // per-thread A gather geometry (fixed across stages)
    const int ar = tid >> 2, akc = tid & 3;
    const int m = bm + ar;
    const bool valid = (m < BL);
    int b = m / NPATCH;
    int l = m - b * NPATCH;
    int ih = l / NP;
    int iw = l - ih * NP;
    const __nv_bfloat16* aptr =
        valid ? g_Xb + ((size_t)b << 22) + (ih * 4 + akc) * 256 + iw * 4 : g_Xb;
    const uint32_t asz = valid ? 8u : 0u;
    const uint32_t asw = sw_off(ar, akc);

    float acc[2][8][4];
#pragma unroll
    for (int i = 0; i < 2; i++)
#pragma unroll
        for (int j = 0; j < 8; j++)
#pragma unroll
            for (int k = 0; k < 4; k++) acc[i][j][k] = 0.0f;

    auto load_stage = [&](int kt) {
        uint32_t sA = smem + (kt & 3) * STAGE_BYTES;
        uint32_t sB = sA + ABYTES;
        // A: gather from g_Xb. chunk offset: c*65536 + kh0*256 elements
        const __nv_bfloat16* as = aptr + ((kt >> 1) << 16) + ((kt & 1) << 10);
        cp_async8z(sA + asw, as, asz);
        cp_async8z(sA + asw + 8, as + 4, asz);
        // B: W1 rows (K-major, stride 4096)
        const __nv_bfloat16* Bg = g_W1 + kt * 32;
#pragma unroll
        for (int i = 0; i < 2; i++) {
            int q = tid + (i << 9);
            int r = q >> 2, kc = q & 3;
            cp_async16(sB + sw_off(r, kc), Bg + (long)r * K + (kc << 3));
        }
    };

    load_stage(0); cp_commit();
    load_stage(1); cp_commit();
    load_stage(2); cp_commit();

    for (int kt = 0; kt < KT; kt++) {
        if (kt + 2 < KT) cp_wait<2>(); else cp_wait<0>();
        __syncthreads();
        int kn = kt + 3;
        if (kn < KT) load_stage(kn);
        cp_commit();

        uint32_t sA = smem + (kt & 3) * STAGE_BYTES;
        uint32_t sB = sA + ABYTES;
#pragma unroll
        for (int kk = 0; kk < 2; kk++) {
            uint32_t a[2][4];
#pragma unroll
            for (int mi = 0; mi < 2; mi++) {
                int r = wm * 32 + mi * 16 + (lane & 15);
                int kc = (kk << 1) | (lane >> 4);
                ldmx4(a[mi][0], a[mi][1], a[mi][2], a[mi][3], sA + sw_off(r, kc));
            }
            uint32_t bfr[8][2];
#pragma unroll
            for (int nj = 0; nj < 4; nj++) {
                int r = wn * 64 + nj * 16 + (lane & 7) + ((lane & 16) >> 1);
                int kc = (kk << 1) | ((lane >> 3) & 1);
                uint32_t t0, t1, t2, t3;
                ldmx4(t0, t1, t2, t3, sB + sw_off(r, kc));
                bfr[nj * 2][0] = t0; bfr[nj * 2][1] = t1;
                bfr[nj * 2 + 1][0] = t2; bfr[nj * 2 + 1][1] = t3;
            }
#pragma unroll
            for (int mi = 0; mi < 2; mi++)
#pragma unroll
                for (int ni = 0; ni < 8; ni++) mma16816(acc[mi][ni], a[mi], bfr[ni]);
        }
    }

    const long crow = bm + wm * 32 + (lane >> 2);
#pragma unroll
    for (int mi = 0; mi < 2; mi++) {
#pragma unroll
        for (int ni = 0; ni < 8; ni++) {
            long col = wn * 64 + ni * 8 + ((lane & 3) << 1);
            float b0 = bias[col], b1 = bias[col + 1];
            float v0 = gelu_exact(acc[mi][ni][0] + b0);
            float v1 = gelu_exact(acc[mi][ni][1] + b1);
            float v2 = gelu_exact(acc[mi][ni][2] + b0);
            float v3 = gelu_exact(acc[mi][ni][3] + b1);
            long r0 = crow + mi * 16;
            *(__nv_bfloat162*)(H + r0 * N + col) = __floats2bfloat162_rn(v0, v1);
            *(__nv_bfloat162*)(H + (r0 + 8) * N + col) = __floats2bfloat162_rn(v2, v3);
        }
    }
}

// ---------------------------------------------------------------------------
// Kernel 3: GEMM2  Y = H @ W2^T + b2.  128x128x32 tiles, 256 threads,
// __launch_bounds__(256,2) -> 2 CTAs/SM so pipeline fill overlaps compute.
// ---------------------------------------------------------------------------
__global__ void __launch_bounds__(256, 2)
gemm2(const __nv_bfloat16* __restrict__ A, const __nv_bfloat16* __restrict__ Bw,
      const float* __restrict__ bias, __nv_bfloat16* __restrict__ C) {
    constexpr int ABYTES = 8192;   // 128 x 32
    constexpr int BBYTES = 8192;   // 128 x 32
    constexpr int STAGE_BYTES = ABYTES + BBYTES;  // 16 KB, 4 stages = 64 KB
    constexpr int K = 256, N = 4096, KT = 8;
    extern __shared__ __align__(128) uint8_t smem_raw[];
    const uint32_t smem = (uint32_t)__cvta_generic_to_shared(smem_raw);

    const int tid = threadIdx.x;
    const int lane = tid & 31, warp = tid >> 5;
    const int wm = warp >> 1, wn = warp & 1;
    const long bm = (long)blockIdx.x * 128;
    const long bn = (long)blockIdx.y * 128;

    float acc[2][8][4];
#pragma unroll
    for (int i = 0; i < 2; i++)
#pragma unroll
        for (int j = 0; j < 8; j++)
#pragma unroll
            for (int k = 0; k < 4; k++) acc[i][j][k] = 0.0f;

    auto load_stage = [&](int kt) {
        const __nv_bfloat16* Ag = A + bm * K + kt * 32;
        const __nv_bfloat16* Bg = Bw + bn * K + kt * 32;
        uint32_t sA = smem + (kt & 3) * STAGE_BYTES;
        uint32_t sB = sA + ABYTES;
#pragma unroll
        for (int i = 0; i < 2; i++) {
            int q = tid + (i << 8);
            int r = q >> 2, kc = q & 3;
            cp_async16(sA + sw_off(r, kc), Ag + (long)r * K + (kc << 3));
        }
#pragma unroll
        for (int i = 0; i < 2; i++) {
            int q = tid + (i << 8);
            int r = q >> 2, kc = q & 3;
            cp_async16(sB + sw_off(r, kc), Bg + (long)r * K + (kc << 3));
        }
    };

    load_stage(0); cp_commit();
    load_stage(1); cp_commit();
    load_stage(2); cp_commit();

    for (int kt = 0; kt < KT; kt++) {
        if (kt + 2 < KT) cp_wait<2>(); else cp_wait<0>();
        __syncthreads();
        int kn = kt + 3;
        if (kn < KT) load_stage(kn);
        cp_commit();

        uint32_t sA = smem + (kt & 3) * STAGE_BYTES;
        uint32_t sB = sA + ABYTES;
#pragma unroll
        for (int kk = 0; kk < 2; kk++) {
            uint32_t a[2][4];
#pragma unroll
            for (int mi = 0; mi < 2; mi++) {
                int r = wm * 32 + mi * 16 + (lane & 15);
                int kc = (kk << 1) | (lane >> 4);
                ldmx4(a[mi][0], a[mi][1], a[mi][2], a[mi][3], sA + sw_off(r, kc));
            }
            uint32_t bfr[8][2];
#pragma unroll
            for (int nj = 0; nj < 4; nj++) {
                int r = wn * 64 + nj * 16 + (lane & 7) + ((lane & 16) >> 1);
                int kc = (kk << 1) | ((lane >> 3) & 1);
                uint32_t t0, t1, t2, t3;
                ldmx4(t0, t1, t2, t3, sB + sw_off(r, kc));
                bfr[nj * 2][0] = t0; bfr[nj * 2][1] = t1;
                bfr[nj * 2 + 1][0] = t2; bfr[nj * 2 + 1][1] = t3;
            }
#pragma unroll
            for (int mi = 0; mi < 2; mi++)
#pragma unroll
                for (int ni = 0; ni < 8; ni++) mma16816(acc[mi][ni], a[mi], bfr[ni]);
        }
    }

    const long crow = bm + wm * 32 + (lane >> 2);
#pragma unroll
    for (int mi = 0; mi < 2; mi++) {
#pragma unroll
        for (int ni = 0; ni < 8; ni++) {
            long col = bn + wn * 64 + ni * 8 + ((lane & 3) << 1);
            float b0 = bias[col], b1 = bias[col + 1];
            float v0 = acc[mi][ni][0] + b0;
            float v1 = acc[mi][ni][1] + b1;
            float v2 = acc[mi][ni][2] + b0;
            float v3 = acc[mi][ni][3] + b1;
            long r0 = crow + mi * 16;
            *(__nv_bfloat162*)(C + r0 * N + col) = __floats2bfloat162_rn(v0, v1);
            *(__nv_bfloat162*)(C + (r0 + 8) * N + col) = __floats2bfloat162_rn(v2, v3);
        }
    }
}

// ---------------------------------------------------------------------------
// Kernel 4: gather-fold + residual
// out = x + softplus(alpha_raw) * fold(Y)/norm   (fold(P)/norm == x exactly)
// ---------------------------------------------------------------------------
__global__ void fold_kernel(const float* __restrict__ x,
                            const float* __restrict__ alpha_raw,
                            float* __restrict__ out) {
    int t = blockIdx.x * 256 + threadIdx.x;  // 4,194,304 threads
    int w0 = (t & 63) << 2;
    int h = (t >> 6) & 255;
    int c = (t >> 14) & 63;
    int b = t >> 20;

    float alpha = log1pf(__expf(alpha_raw[0]));

    int ih_lo = max(0, (h - 4) >> 2);
    int ih_hi = min(62, h >> 2);
    int iw_lo = max(0, (w0 - 4) >> 2);
    int iw_hi = min(62, w0 >> 2);
    int cnt = (ih_hi - ih_lo + 1) * (iw_hi - iw_lo + 1);

    float s0 = 0.f, s1 = 0.f, s2 = 0.f, s3 = 0.f;
    for (int ih = ih_lo; ih <= ih_hi; ih++) {
        int kh = h - 4 * ih;
        for (int iw = iw_lo; iw <= iw_hi; iw++) {
            int kw0 = w0 - 4 * iw;
            size_t m = (size_t)b * NPATCH + ih * NP + iw;
            const __nv_bfloat162* p =
                (const __nv_bfloat162*)(g_Y + m * IND + c * 64 + kh * 8 + kw0);
            __nv_bfloat162 v01 = p[0];
            __nv_bfloat162 v23 = p[1];
            s0 += __low2float(v01); s1 += __high2float(v01);
            s2 += __low2float(v23); s3 += __high2float(v23);
        }
    }
    float sc = alpha / (float)cnt;
    size_t xi = (size_t)t * 4;
    float4 xv = *(const float4*)(x + xi);
    float4 o;
    o.x = fmaf(s0, sc, xv.x);
    o.y = fmaf(s1, sc, xv.y);
    o.z = fmaf(s2, sc, xv.z);
    o.w = fmaf(s3, sc, xv.w);
    *(float4*)(out + xi) = o;
}

// ---------------------------------------------------------------------------
// Launch
// ---------------------------------------------------------------------------
extern "C" void kernel_launch(void* const* d_in, const int* in_sizes, int n_in,
                              void* d_out, int out_size) {
    const float* x         = (const float*)d_in[0];
    const float* W1        = (const float*)d_in[1];
    const float* b1        = (const float*)d_in[2];
    const float* W2        = (const float*)d_in[3];
    const float* b2        = (const float*)d_in[4];
    const float* alpha_raw = (const float*)d_in[5];
    float* out             = (float*)d_out;

    void *pH, *pY, *pW2;
    cudaGetSymbolAddress(&pH, g_H);
    cudaGetSymbolAddress(&pY, g_Y);
    cudaGetSymbolAddress(&pW2, g_W2);

    const int SM1 = 4 * 24576;  // 96 KB
    const int SM2 = 4 * 16384;  // 64 KB
    cudaFuncSetAttribute(gemm1_fused,
                         cudaFuncAttributeMaxDynamicSharedMemorySize, SM1);
    cudaFuncSetAttribute(gemm2,
                         cudaFuncAttributeMaxDynamicSharedMemorySize, SM2);

    convert_weights<<<1024, 256>>>(W1, W2);
    convert_x<<<16384, 256>>>(x);
    // GEMM1 (+patchify): H = GELU(P @ W1^T + b1)  M=16000, N=256, K=4096
    gemm1_fused<<<125, 512, SM1>>>(b1, (__nv_bfloat16*)pH);
    // GEMM2: Y = H @ W2^T + b2                    M=16000, N=4096, K=256
    gemm2<<<dim3(125, 32), 256, SM2>>>(
        (const __nv_bfloat16*)pH, (const __nv_bfloat16*)pW2, b2,
        (__nv_bfloat16*)pY);
    fold_kernel<<<16384, 256>>>(x, alpha_raw, out);
}